// round 5
// baseline (speedup 1.0000x reference)
#include <cuda_runtime.h>
#include <math.h>
#include <stdint.h>

#define NN    100000
#define E1N   1600000
#define E2N   1600000
#define IN_D  128
#define H1_D  128
#define H2_D  64
#define MH_D  128

// ---------------- scratch (device globals; no runtime allocation) ----------------
__device__ __align__(16) float g_deg[NN];
__device__ __align__(16) float g_invdeg[NN];
__device__ __align__(16) float g_agg1[NN * IN_D];        // 12.8M  layer-1 neighbor sum
__device__ __align__(16) float g_big[NN * 256];          // 25.6M  cat1 then A|B (reused)
__device__ __align__(16) float g_h1[NN * H1_D];          // 12.8M
__device__ __align__(16) float g_l2out[NN * 128];        // cols 0-63: h1@Wself2, 64-127: t1 = h1@Wneigh2
__device__ __align__(16) float g_agg2[NN * H2_D];        // 6.4M
__device__ __align__(16) float g_h[NN * H2_D];           // 6.4M  final node embeddings
__device__ __align__(16) float g_Wcat1[256 * 128];       // [Wself1; Wneigh1]
__device__ __align__(16) float g_Wcat2[128 * 128];       // [Wself2 | Wneigh2]
__device__ __align__(16) float g_Wab[64 * 256];          // [Wmlp1_top | Wmlp1_bot]

// ---------------- helpers ----------------
__device__ __forceinline__ void red4(float* p, float4 v) {
    asm volatile("red.global.add.v4.f32 [%0], {%1, %2, %3, %4};"
                 :: "l"(p), "f"(v.x), "f"(v.y), "f"(v.z), "f"(v.w) : "memory");
}

// ---------------- kernels ----------------
__global__ void k_zero() {
    long i = (long)blockIdx.x * blockDim.x + threadIdx.x;
    long stride = (long)gridDim.x * blockDim.x;
    for (long j = i; j < (long)NN * IN_D; j += stride) g_agg1[j] = 0.f;
    for (long j = i; j < (long)NN * H2_D; j += stride) g_agg2[j] = 0.f;
    for (long j = i; j < NN; j += stride) g_deg[j] = 0.f;
}

__global__ void k_pack(const float* __restrict__ Ws1, const float* __restrict__ Wn1,
                       const float* __restrict__ Ws2, const float* __restrict__ Wn2,
                       const float* __restrict__ Wm1) {
    int i = blockIdx.x * blockDim.x + threadIdx.x;
    int stride = gridDim.x * blockDim.x;
    for (int j = i; j < 256 * 128; j += stride)
        g_Wcat1[j] = (j < 128 * 128) ? Ws1[j] : Wn1[j - 128 * 128];
    for (int j = i; j < 128 * 128; j += stride) {
        int k = j >> 7, c = j & 127;
        g_Wcat2[j] = (c < 64) ? Ws2[k * 64 + c] : Wn2[k * 64 + (c - 64)];
    }
    for (int j = i; j < 64 * 256; j += stride) {
        int k = j >> 8, c = j & 255;
        g_Wab[j] = (c < 128) ? Wm1[k * 128 + c] : Wm1[(64 + k) * 128 + (c - 128)];
    }
}

__global__ void k_deg(const int* __restrict__ dst) {
    int i = blockIdx.x * blockDim.x + threadIdx.x;
    int stride = gridDim.x * blockDim.x;
    for (int e = i; e < E1N; e += stride)
        atomicAdd(&g_deg[dst[e]], 1.0f);
}

__global__ void k_invdeg() {
    int i = blockIdx.x * blockDim.x + threadIdx.x;
    if (i < NN) g_invdeg[i] = 1.0f / fmaxf(g_deg[i], 1.0f);
}

// layer-1 scatter: one warp per edge, 128 floats as 32 x float4
__global__ void k_scatter1(const int* __restrict__ src, const int* __restrict__ dst,
                           const float* __restrict__ x) {
    int lane = threadIdx.x & 31;
    int warp = (blockIdx.x * blockDim.x + threadIdx.x) >> 5;
    int nwarps = (gridDim.x * blockDim.x) >> 5;
    for (int e = warp; e < E1N; e += nwarps) {
        int s = src[e], d = dst[e];
        float4 v = *(const float4*)&x[(size_t)s * 128 + lane * 4];
        red4(&g_agg1[(size_t)d * 128 + lane * 4], v);
    }
}

// build concat([x, agg1*invdeg]) rows of 256
__global__ void k_cat1(const float* __restrict__ x) {
    int idx = blockIdx.x * blockDim.x + threadIdx.x;  // over NN*64 float4 slots
    if (idx >= NN * 64) return;
    int i = idx >> 6;
    int c = (idx & 63) * 4;
    float4 v;
    if (c < 128) {
        v = *(const float4*)&x[(size_t)i * 128 + c];
    } else {
        v = *(const float4*)&g_agg1[(size_t)i * 128 + (c - 128)];
        float s = g_invdeg[i];
        v.x *= s; v.y *= s; v.z *= s; v.w *= s;
    }
    *(float4*)&g_big[(size_t)i * 256 + c] = v;
}

// classic 64x64 tiled SGEMM, BK=16, 256 threads, 4x4 per-thread tile
template<bool RELU, bool BIAS>
__global__ void sgemm_k(const float* __restrict__ A, const float* __restrict__ W,
                        const float* __restrict__ bias, float* __restrict__ C,
                        int M, int K, int Ncol) {
    __shared__ float As[16][65];
    __shared__ float Ws[16][64];
    const int tid = threadIdx.x;
    const int trow = tid >> 4;        // 0..15
    const int tcol = tid & 15;        // 0..15
    const int row0 = blockIdx.x * 64;
    const int col0 = blockIdx.y * 64;
    const int arow = tid >> 2;        // 0..63
    const int ak   = (tid & 3) << 2;  // 0,4,8,12
    const int wk   = tid >> 4;        // 0..15
    const int wn   = (tid & 15) << 2; // 0..60
    float acc[4][4] = {};
    for (int k0 = 0; k0 < K; k0 += 16) {
        float4 av = make_float4(0.f, 0.f, 0.f, 0.f);
        if (row0 + arow < M)
            av = *(const float4*)&A[(size_t)(row0 + arow) * K + k0 + ak];
        As[ak + 0][arow] = av.x;
        As[ak + 1][arow] = av.y;
        As[ak + 2][arow] = av.z;
        As[ak + 3][arow] = av.w;
        *(float4*)&Ws[wk][wn] = *(const float4*)&W[(size_t)(k0 + wk) * Ncol + col0 + wn];
        __syncthreads();
#pragma unroll
        for (int k = 0; k < 16; k++) {
            float a0 = As[k][trow * 4 + 0];
            float a1 = As[k][trow * 4 + 1];
            float a2 = As[k][trow * 4 + 2];
            float a3 = As[k][trow * 4 + 3];
            float4 w4 = *(const float4*)&Ws[k][tcol * 4];
            acc[0][0] += a0 * w4.x; acc[0][1] += a0 * w4.y; acc[0][2] += a0 * w4.z; acc[0][3] += a0 * w4.w;
            acc[1][0] += a1 * w4.x; acc[1][1] += a1 * w4.y; acc[1][2] += a1 * w4.z; acc[1][3] += a1 * w4.w;
            acc[2][0] += a2 * w4.x; acc[2][1] += a2 * w4.y; acc[2][2] += a2 * w4.z; acc[2][3] += a2 * w4.w;
            acc[3][0] += a3 * w4.x; acc[3][1] += a3 * w4.y; acc[3][2] += a3 * w4.z; acc[3][3] += a3 * w4.w;
        }
        __syncthreads();
    }
    float4 bb = make_float4(0.f, 0.f, 0.f, 0.f);
    if (BIAS) bb = *(const float4*)&bias[col0 + tcol * 4];
#pragma unroll
    for (int i = 0; i < 4; i++) {
        int row = row0 + trow * 4 + i;
        if (row < M) {
            float4 r = make_float4(acc[i][0], acc[i][1], acc[i][2], acc[i][3]);
            if (BIAS) { r.x += bb.x; r.y += bb.y; r.z += bb.z; r.w += bb.w; }
            if (RELU) {
                r.x = fmaxf(r.x, 0.f); r.y = fmaxf(r.y, 0.f);
                r.z = fmaxf(r.z, 0.f); r.w = fmaxf(r.w, 0.f);
            }
            *(float4*)&C[(size_t)row * Ncol + col0 + tcol * 4] = r;
        }
    }
}

// layer-2 scatter in transformed 64-dim space: two edges per warp (16 lanes each)
__global__ void k_scatter2(const int* __restrict__ src, const int* __restrict__ dst) {
    int lane = threadIdx.x & 31;
    int warp = (blockIdx.x * blockDim.x + threadIdx.x) >> 5;
    int nwarps = (gridDim.x * blockDim.x) >> 5;
    int half = lane >> 4;
    int sub = lane & 15;
    for (int e0 = warp * 2; e0 < E1N; e0 += nwarps * 2) {
        int e = e0 + half;
        if (e < E1N) {
            int s = src[e], d = dst[e];
            float4 v = *(const float4*)&g_l2out[(size_t)s * 128 + 64 + sub * 4];
            red4(&g_agg2[(size_t)d * 64 + sub * 4], v);
        }
    }
}

__global__ void k_combine2(const float* __restrict__ b2, float* __restrict__ outh) {
    int idx = blockIdx.x * blockDim.x + threadIdx.x;  // over NN*16 float4 slots
    if (idx >= NN * 16) return;
    int i = idx >> 4;
    int c = (idx & 15) * 4;
    float4 sf = *(const float4*)&g_l2out[(size_t)i * 128 + c];
    float4 ag = *(const float4*)&g_agg2[(size_t)i * 64 + c];
    float id = g_invdeg[i];
    float4 bb = *(const float4*)&b2[c];
    float4 r;
    r.x = fmaxf(sf.x + ag.x * id + bb.x, 0.f);
    r.y = fmaxf(sf.y + ag.y * id + bb.y, 0.f);
    r.z = fmaxf(sf.z + ag.z * id + bb.z, 0.f);
    r.w = fmaxf(sf.w + ag.w * id + bb.w, 0.f);
    *(float4*)&g_h[(size_t)i * 64 + c] = r;
    if (outh) *(float4*)&outh[(size_t)i * 64 + c] = r;
}

// edge scoring: warp per edge; h2 = relu(A[s]+B[d]+b_mlp1); score = sigmoid(h2.w2 + b_mlp2)
__global__ void k_edge(const int* __restrict__ ss, const int* __restrict__ sd,
                       const float* __restrict__ bm1, const float* __restrict__ wm2,
                       const float* __restrict__ bm2, float* __restrict__ out) {
    int lane = threadIdx.x & 31;
    int warp = (blockIdx.x * blockDim.x + threadIdx.x) >> 5;
    int nwarps = (gridDim.x * blockDim.x) >> 5;
    float4 bias = *(const float4*)&bm1[lane * 4];
    float4 w = *(const float4*)&wm2[lane * 4];
    float bo = bm2[0];
    for (int e = warp; e < E2N; e += nwarps) {
        int s = ss[e], d = sd[e];
        float4 a = *(const float4*)&g_big[(size_t)s * 256 + lane * 4];
        float4 b = *(const float4*)&g_big[(size_t)d * 256 + 128 + lane * 4];
        float v0 = fmaxf(a.x + b.x + bias.x, 0.f);
        float v1 = fmaxf(a.y + b.y + bias.y, 0.f);
        float v2 = fmaxf(a.z + b.z + bias.z, 0.f);
        float v3 = fmaxf(a.w + b.w + bias.w, 0.f);
        float p = v0 * w.x + v1 * w.y + v2 * w.z + v3 * w.w;
        p += __shfl_xor_sync(0xFFFFFFFFu, p, 16);
        p += __shfl_xor_sync(0xFFFFFFFFu, p, 8);
        p += __shfl_xor_sync(0xFFFFFFFFu, p, 4);
        p += __shfl_xor_sync(0xFFFFFFFFu, p, 2);
        p += __shfl_xor_sync(0xFFFFFFFFu, p, 1);
        if (lane == 0)
            out[e] = 1.0f / (1.0f + expf(-(p + bo)));
    }
}

// ---------------- launch ----------------
extern "C" void kernel_launch(void* const* d_in, const int* in_sizes, int n_in,
                              void* d_out, int out_size) {
    const float* x    = (const float*)d_in[0];
    const int*   esrc = (const int*)d_in[1];
    const int*   edst = (const int*)d_in[2];
    const int*   ssrc = (const int*)d_in[3];
    const int*   sdst = (const int*)d_in[4];
    const float* Ws1  = (const float*)d_in[5];
    const float* Wn1  = (const float*)d_in[6];
    const float* b1   = (const float*)d_in[7];
    const float* Ws2  = (const float*)d_in[8];
    const float* Wn2  = (const float*)d_in[9];
    const float* b2   = (const float*)d_in[10];
    const float* Wm1  = (const float*)d_in[11];
    const float* bm1  = (const float*)d_in[12];
    const float* Wm2  = (const float*)d_in[13];
    const float* bm2  = (const float*)d_in[14];

    float* out = (float*)d_out;
    float* outh = (out_size >= E2N + NN * H2_D) ? out + E2N : nullptr;

    float *p_big, *p_h1, *p_l2out, *p_h, *p_W1, *p_W2, *p_Wab;
    cudaGetSymbolAddress((void**)&p_big,   g_big);
    cudaGetSymbolAddress((void**)&p_h1,    g_h1);
    cudaGetSymbolAddress((void**)&p_l2out, g_l2out);
    cudaGetSymbolAddress((void**)&p_h,     g_h);
    cudaGetSymbolAddress((void**)&p_W1,    g_Wcat1);
    cudaGetSymbolAddress((void**)&p_W2,    g_Wcat2);
    cudaGetSymbolAddress((void**)&p_Wab,   g_Wab);

    k_zero<<<2368, 256>>>();
    k_pack<<<64, 256>>>(Ws1, Wn1, Ws2, Wn2, Wm1);
    k_deg<<<2368, 256>>>(edst);
    k_invdeg<<<(NN + 255) / 256, 256>>>();
    k_scatter1<<<4096, 256>>>(esrc, edst, x);
    k_cat1<<<(NN * 64 + 255) / 256, 256>>>(x);
    // layer 1: h1 = relu([x|agg] @ [Wself1;Wneigh1] + b1)
    sgemm_k<true, true><<<dim3((NN + 63) / 64, 128 / 64), 256>>>(p_big, p_W1, b1, p_h1, NN, 256, 128);
    // layer 2 dense part: [h1@Wself2 | h1@Wneigh2]
    sgemm_k<false, false><<<dim3((NN + 63) / 64, 128 / 64), 256>>>(p_h1, p_W2, nullptr, p_l2out, NN, 128, 128);
    k_scatter2<<<4096, 256>>>(esrc, edst);
    k_combine2<<<(NN * 16 + 255) / 256, 256>>>(b2, outh);
    // A|B = h @ [Wmlp1_top | Wmlp1_bot]
    sgemm_k<false, false><<<dim3((NN + 63) / 64, 256 / 64), 256>>>(p_h, p_Wab, nullptr, p_big, NN, 64, 256);
    k_edge<<<4096, 256>>>(ssrc, sdst, bm1, Wm2, bm2, out);
}

// round 10
// speedup vs baseline: 1.0408x; 1.0408x over previous
#include <cuda_runtime.h>
#include <math.h>
#include <stdint.h>

#define NN    100000
#define E1N   1600000
#define E2N   1600000
#define IN_D  128
#define H1_D  128
#define H2_D  64
#define MH_D  128

typedef unsigned long long ull;

// ---------------- scratch (device globals; no runtime allocation) ----------------
__device__ __align__(16) float g_deg[NN];
__device__ __align__(16) float g_invdeg[NN];
__device__ __align__(16) float g_agg1[NN * IN_D];        // layer-1 neighbor sum
__device__ __align__(16) float g_big[NN * 256];          // cat1 then A|B (reused)
__device__ __align__(16) float g_h1[NN * H1_D];
__device__ __align__(16) float g_l2out[NN * 128];        // cols 0-63: h1@Wself2, 64-127: h1@Wneigh2
__device__ __align__(16) float g_agg2[NN * H2_D];
__device__ __align__(16) float g_h[NN * H2_D];           // final node embeddings
__device__ __align__(16) float g_Wcat1[256 * 128];       // [Wself1; Wneigh1]
__device__ __align__(16) float g_Wcat2[128 * 128];       // [Wself2 | Wneigh2]
__device__ __align__(16) float g_Wab[64 * 256];          // [Wmlp1_top | Wmlp1_bot]

// ---------------- helpers ----------------
__device__ __forceinline__ void red4(float* p, float4 v) {
    asm volatile("red.global.add.v4.f32 [%0], {%1, %2, %3, %4};"
                 :: "l"(p), "f"(v.x), "f"(v.y), "f"(v.z), "f"(v.w) : "memory");
}

// packed f32x2 (Blackwell FFMA2 path — 2x fp32 per issue slot)
__device__ __forceinline__ ull pack2(float x, float y) {
    ull r;
    asm("mov.b64 %0, {%1, %2};" : "=l"(r) : "f"(x), "f"(y));
    return r;
}
__device__ __forceinline__ ull fma2(ull a, ull b, ull c) {
    ull d;
    asm("fma.rn.f32x2 %0, %1, %2, %3;" : "=l"(d) : "l"(a), "l"(b), "l"(c));
    return d;
}
__device__ __forceinline__ float2 unpack2(ull v) {
    float2 f;
    asm("mov.b64 {%0, %1}, %2;" : "=f"(f.x), "=f"(f.y) : "l"(v));
    return f;
}

// ---------------- kernels ----------------
__global__ void k_zero() {
    long i = (long)blockIdx.x * blockDim.x + threadIdx.x;
    long stride = (long)gridDim.x * blockDim.x;
    for (long j = i; j < (long)NN * IN_D; j += stride) g_agg1[j] = 0.f;
    for (long j = i; j < (long)NN * H2_D; j += stride) g_agg2[j] = 0.f;
    for (long j = i; j < NN; j += stride) g_deg[j] = 0.f;
}

__global__ void k_pack(const float* __restrict__ Ws1, const float* __restrict__ Wn1,
                       const float* __restrict__ Ws2, const float* __restrict__ Wn2,
                       const float* __restrict__ Wm1) {
    int i = blockIdx.x * blockDim.x + threadIdx.x;
    int stride = gridDim.x * blockDim.x;
    for (int j = i; j < 256 * 128; j += stride)
        g_Wcat1[j] = (j < 128 * 128) ? Ws1[j] : Wn1[j - 128 * 128];
    for (int j = i; j < 128 * 128; j += stride) {
        int k = j >> 7, c = j & 127;
        g_Wcat2[j] = (c < 64) ? Ws2[k * 64 + c] : Wn2[k * 64 + (c - 64)];
    }
    for (int j = i; j < 64 * 256; j += stride) {
        int k = j >> 8, c = j & 255;
        g_Wab[j] = (c < 128) ? Wm1[k * 128 + c] : Wm1[(64 + k) * 128 + (c - 128)];
    }
}

__global__ void k_deg(const int* __restrict__ dst) {
    int i = blockIdx.x * blockDim.x + threadIdx.x;
    int stride = gridDim.x * blockDim.x;
    for (int e = i; e < E1N; e += stride)
        atomicAdd(&g_deg[dst[e]], 1.0f);
}

__global__ void k_invdeg() {
    int i = blockIdx.x * blockDim.x + threadIdx.x;
    if (i < NN) g_invdeg[i] = 1.0f / fmaxf(g_deg[i], 1.0f);
}

// layer-1 scatter: one warp per edge, 128 floats as 32 x float4
__global__ void k_scatter1(const int* __restrict__ src, const int* __restrict__ dst,
                           const float* __restrict__ x) {
    int lane = threadIdx.x & 31;
    int warp = (blockIdx.x * blockDim.x + threadIdx.x) >> 5;
    int nwarps = (gridDim.x * blockDim.x) >> 5;
    for (int e = warp; e < E1N; e += nwarps) {
        int s = src[e], d = dst[e];
        float4 v = *(const float4*)&x[(size_t)s * 128 + lane * 4];
        red4(&g_agg1[(size_t)d * 128 + lane * 4], v);
    }
}

// build concat([x, agg1*invdeg]) rows of 256
__global__ void k_cat1(const float* __restrict__ x) {
    int idx = blockIdx.x * blockDim.x + threadIdx.x;
    if (idx >= NN * 64) return;
    int i = idx >> 6;
    int c = (idx & 63) * 4;
    float4 v;
    if (c < 128) {
        v = *(const float4*)&x[(size_t)i * 128 + c];
    } else {
        v = *(const float4*)&g_agg1[(size_t)i * 128 + (c - 128)];
        float s = g_invdeg[i];
        v.x *= s; v.y *= s; v.z *= s; v.w *= s;
    }
    *(float4*)&g_big[(size_t)i * 256 + c] = v;
}

// ---------------- 128x128 tiled SGEMM, BK=16, 256 threads, 8x8/thread, FFMA2 ----------------
// C[M,Ncol] = A[M,K] @ W[K,Ncol] (+bias)(+relu).  K % 16 == 0, Ncol % 128 == 0.
template<bool RELU, bool BIAS>
__global__ __launch_bounds__(256) void sgemm2_k(
        const float* __restrict__ A, const float* __restrict__ W,
        const float* __restrict__ bias, float* __restrict__ C,
        int M, int K, int Ncol) {
    __shared__ float As[16][132];   // +4 pad: breaks transpose-store conflicts, keeps 16B align
    __shared__ float Ws[16][128];
    const int tid  = threadIdx.x;
    const int ty   = tid >> 4;          // 0..15  (row group, 8 rows each)
    const int tx   = tid & 15;          // 0..15  (col group, 8 cols each)
    const int row0 = blockIdx.x * 128;
    const int col0 = blockIdx.y * 128;

    // A-tile load mapping: 512 float4 slots, 2 per thread; slot s -> row=s>>2, kq=(s&3)*4
    const int ar0 = tid >> 2;            // rows for slot tid
    const int ak0 = (tid & 3) << 2;
    const int ar1 = (tid + 256) >> 2;    // rows for slot tid+256
    const int ak1 = ((tid + 256) & 3) << 2;
    // W-tile load mapping: slot s -> k=s>>5, c=(s&31)*4
    const int wk0 = tid >> 5;
    const int wc0 = (tid & 31) << 2;
    const int wk1 = (tid + 256) >> 5;
    const int wc1 = ((tid + 256) & 31) << 2;

    ull acc[8][4];
#pragma unroll
    for (int i = 0; i < 8; i++)
#pragma unroll
        for (int j = 0; j < 4; j++) acc[i][j] = pack2(0.f, 0.f);

    for (int k0 = 0; k0 < K; k0 += 16) {
        // load A tile (transposed into As[k][row])
        {
            float4 v = make_float4(0.f, 0.f, 0.f, 0.f);
            if (row0 + ar0 < M)
                v = *(const float4*)&A[(size_t)(row0 + ar0) * K + k0 + ak0];
            As[ak0 + 0][ar0] = v.x; As[ak0 + 1][ar0] = v.y;
            As[ak0 + 2][ar0] = v.z; As[ak0 + 3][ar0] = v.w;
            float4 u = make_float4(0.f, 0.f, 0.f, 0.f);
            if (row0 + ar1 < M)
                u = *(const float4*)&A[(size_t)(row0 + ar1) * K + k0 + ak1];
            As[ak1 + 0][ar1] = u.x; As[ak1 + 1][ar1] = u.y;
            As[ak1 + 2][ar1] = u.z; As[ak1 + 3][ar1] = u.w;
        }
        // load W tile
        *(float4*)&Ws[wk0][wc0] = *(const float4*)&W[(size_t)(k0 + wk0) * Ncol + col0 + wc0];
        *(float4*)&Ws[wk1][wc1] = *(const float4*)&W[(size_t)(k0 + wk1) * Ncol + col0 + wc1];
        __syncthreads();

#pragma unroll
        for (int k = 0; k < 16; k++) {
            float4 a0 = *(const float4*)&As[k][ty * 8];
            float4 a1 = *(const float4*)&As[k][ty * 8 + 4];
            longlong2 wA = *(const longlong2*)&Ws[k][tx * 8];      // 2 packed col-pairs
            longlong2 wB = *(const longlong2*)&Ws[k][tx * 8 + 4];
            ull w0 = (ull)wA.x, w1 = (ull)wA.y, w2 = (ull)wB.x, w3 = (ull)wB.y;
            float av[8] = {a0.x, a0.y, a0.z, a0.w, a1.x, a1.y, a1.z, a1.w};
#pragma unroll
            for (int i = 0; i < 8; i++) {
                ull ad = pack2(av[i], av[i]);
                acc[i][0] = fma2(ad, w0, acc[i][0]);
                acc[i][1] = fma2(ad, w1, acc[i][1]);
                acc[i][2] = fma2(ad, w2, acc[i][2]);
                acc[i][3] = fma2(ad, w3, acc[i][3]);
            }
        }
        __syncthreads();
    }

    float4 bb0 = make_float4(0.f, 0.f, 0.f, 0.f), bb1 = bb0;
    if (BIAS) {
        bb0 = *(const float4*)&bias[col0 + tx * 8];
        bb1 = *(const float4*)&bias[col0 + tx * 8 + 4];
    }
#pragma unroll
    for (int i = 0; i < 8; i++) {
        int row = row0 + ty * 8 + i;
        if (row < M) {
            float2 p0 = unpack2(acc[i][0]);
            float2 p1 = unpack2(acc[i][1]);
            float2 p2 = unpack2(acc[i][2]);
            float2 p3 = unpack2(acc[i][3]);
            float4 r0 = make_float4(p0.x, p0.y, p1.x, p1.y);
            float4 r1 = make_float4(p2.x, p2.y, p3.x, p3.y);
            if (BIAS) {
                r0.x += bb0.x; r0.y += bb0.y; r0.z += bb0.z; r0.w += bb0.w;
                r1.x += bb1.x; r1.y += bb1.y; r1.z += bb1.z; r1.w += bb1.w;
            }
            if (RELU) {
                r0.x = fmaxf(r0.x, 0.f); r0.y = fmaxf(r0.y, 0.f);
                r0.z = fmaxf(r0.z, 0.f); r0.w = fmaxf(r0.w, 0.f);
                r1.x = fmaxf(r1.x, 0.f); r1.y = fmaxf(r1.y, 0.f);
                r1.z = fmaxf(r1.z, 0.f); r1.w = fmaxf(r1.w, 0.f);
            }
            *(float4*)&C[(size_t)row * Ncol + col0 + tx * 8]     = r0;
            *(float4*)&C[(size_t)row * Ncol + col0 + tx * 8 + 4] = r1;
        }
    }
}

// layer-2 scatter in transformed 64-dim space: two edges per warp (16 lanes each)
__global__ void k_scatter2(const int* __restrict__ src, const int* __restrict__ dst) {
    int lane = threadIdx.x & 31;
    int warp = (blockIdx.x * blockDim.x + threadIdx.x) >> 5;
    int nwarps = (gridDim.x * blockDim.x) >> 5;
    int half = lane >> 4;
    int sub = lane & 15;
    for (int e0 = warp * 2; e0 < E1N; e0 += nwarps * 2) {
        int e = e0 + half;
        if (e < E1N) {
            int s = src[e], d = dst[e];
            float4 v = *(const float4*)&g_l2out[(size_t)s * 128 + 64 + sub * 4];
            red4(&g_agg2[(size_t)d * 64 + sub * 4], v);
        }
    }
}

__global__ void k_combine2(const float* __restrict__ b2, float* __restrict__ outh) {
    int idx = blockIdx.x * blockDim.x + threadIdx.x;
    if (idx >= NN * 16) return;
    int i = idx >> 4;
    int c = (idx & 15) * 4;
    float4 sf = *(const float4*)&g_l2out[(size_t)i * 128 + c];
    float4 ag = *(const float4*)&g_agg2[(size_t)i * 64 + c];
    float id = g_invdeg[i];
    float4 bb = *(const float4*)&b2[c];
    float4 r;
    r.x = fmaxf(sf.x + ag.x * id + bb.x, 0.f);
    r.y = fmaxf(sf.y + ag.y * id + bb.y, 0.f);
    r.z = fmaxf(sf.z + ag.z * id + bb.z, 0.f);
    r.w = fmaxf(sf.w + ag.w * id + bb.w, 0.f);
    *(float4*)&g_h[(size_t)i * 64 + c] = r;
    if (outh) *(float4*)&outh[(size_t)i * 64 + c] = r;
}

// edge scoring: warp per edge; h2 = relu(A[s]+B[d]+b_mlp1); score = sigmoid(h2.w2 + b_mlp2)
__global__ void k_edge(const int* __restrict__ ss, const int* __restrict__ sd,
                       const float* __restrict__ bm1, const float* __restrict__ wm2,
                       const float* __restrict__ bm2, float* __restrict__ out) {
    int lane = threadIdx.x & 31;
    int warp = (blockIdx.x * blockDim.x + threadIdx.x) >> 5;
    int nwarps = (gridDim.x * blockDim.x) >> 5;
    float4 bias = *(const float4*)&bm1[lane * 4];
    float4 w = *(const float4*)&wm2[lane * 4];
    float bo = bm2[0];
    for (int e = warp; e < E2N; e += nwarps) {
        int s = ss[e], d = sd[e];
        float4 a = *(const float4*)&g_big[(size_t)s * 256 + lane * 4];
        float4 b = *(const float4*)&g_big[(size_t)d * 256 + 128 + lane * 4];
        float v0 = fmaxf(a.x + b.x + bias.x, 0.f);
        float v1 = fmaxf(a.y + b.y + bias.y, 0.f);
        float v2 = fmaxf(a.z + b.z + bias.z, 0.f);
        float v3 = fmaxf(a.w + b.w + bias.w, 0.f);
        float p = v0 * w.x + v1 * w.y + v2 * w.z + v3 * w.w;
        p += __shfl_xor_sync(0xFFFFFFFFu, p, 16);
        p += __shfl_xor_sync(0xFFFFFFFFu, p, 8);
        p += __shfl_xor_sync(0xFFFFFFFFu, p, 4);
        p += __shfl_xor_sync(0xFFFFFFFFu, p, 2);
        p += __shfl_xor_sync(0xFFFFFFFFu, p, 1);
        if (lane == 0)
            out[e] = 1.0f / (1.0f + expf(-(p + bo)));
    }
}

// ---------------- launch ----------------
extern "C" void kernel_launch(void* const* d_in, const int* in_sizes, int n_in,
                              void* d_out, int out_size) {
    const float* x    = (const float*)d_in[0];
    const int*   esrc = (const int*)d_in[1];
    const int*   edst = (const int*)d_in[2];
    const int*   ssrc = (const int*)d_in[3];
    const int*   sdst = (const int*)d_in[4];
    const float* Ws1  = (const float*)d_in[5];
    const float* Wn1  = (const float*)d_in[6];
    const float* b1   = (const float*)d_in[7];
    const float* Ws2  = (const float*)d_in[8];
    const float* Wn2  = (const float*)d_in[9];
    const float* b2   = (const float*)d_in[10];
    const float* Wm1  = (const float*)d_in[11];
    const float* bm1  = (const float*)d_in[12];
    const float* Wm2  = (const float*)d_in[13];
    const float* bm2  = (const float*)d_in[14];

    float* out = (float*)d_out;
    float* outh = (out_size >= E2N + NN * H2_D) ? out + E2N : nullptr;

    float *p_big, *p_h1, *p_l2out, *p_h, *p_W1, *p_W2, *p_Wab;
    cudaGetSymbolAddress((void**)&p_big,   g_big);
    cudaGetSymbolAddress((void**)&p_h1,    g_h1);
    cudaGetSymbolAddress((void**)&p_l2out, g_l2out);
    cudaGetSymbolAddress((void**)&p_h,     g_h);
    cudaGetSymbolAddress((void**)&p_W1,    g_Wcat1);
    cudaGetSymbolAddress((void**)&p_W2,    g_Wcat2);
    cudaGetSymbolAddress((void**)&p_Wab,   g_Wab);

    k_zero<<<2368, 256>>>();
    k_pack<<<64, 256>>>(Ws1, Wn1, Ws2, Wn2, Wm1);
    k_deg<<<2368, 256>>>(edst);
    k_invdeg<<<(NN + 255) / 256, 256>>>();
    k_scatter1<<<4096, 256>>>(esrc, edst, x);
    k_cat1<<<(NN * 64 + 255) / 256, 256>>>(x);
    // layer 1: h1 = relu([x|agg] @ [Wself1;Wneigh1] + b1)
    sgemm2_k<true, true><<<dim3((NN + 127) / 128, 1), 256>>>(p_big, p_W1, b1, p_h1, NN, 256, 128);
    // layer 2 dense part: [h1@Wself2 | h1@Wneigh2]
    sgemm2_k<false, false><<<dim3((NN + 127) / 128, 1), 256>>>(p_h1, p_W2, nullptr, p_l2out, NN, 128, 128);
    k_scatter2<<<4096, 256>>>(esrc, edst);
    k_combine2<<<(NN * 16 + 255) / 256, 256>>>(b2, outh);
    // A|B = h @ [Wmlp1_top | Wmlp1_bot]
    sgemm2_k<false, false><<<dim3((NN + 127) / 128, 2), 256>>>(p_h, p_Wab, nullptr, p_big, NN, 64, 256);
    k_edge<<<4096, 256>>>(ssrc, sdst, bm1, Wm2, bm2, out);
}